// round 2
// baseline (speedup 1.0000x reference)
#include <cuda_runtime.h>

#define NTOK 25
#define XS_STRIDE 129
#define QK_STRIDE 385
#define WS_STRIDE 17

// Precomputed combined (relative-position bias + window mask) per (window, head, i, j)
__device__ float g_bias[64 * 4 * 25 * 25];

__global__ void bias_kernel(const float* __restrict__ mask, const int* __restrict__ ids_keep,
                            const float* __restrict__ bias_table, const int* __restrict__ rel_index) {
    int w = blockIdx.x;
    __shared__ int ids[NTOK];
    if (threadIdx.x < NTOK) ids[threadIdx.x] = ids_keep[w * NTOK + threadIdx.x];
    __syncthreads();
    for (int e = threadIdx.x; e < 4 * NTOK * NTOK; e += blockDim.x) {
        int h = e / (NTOK * NTOK);
        int r = e % (NTOK * NTOK);
        int i = r / NTOK, j = r % NTOK;
        int ia = ids[i], ja = ids[j];
        int rel = rel_index[ia * 49 + ja];
        g_bias[(w * 4 + h) * 625 + r] = bias_table[rel * 4 + h] + mask[(w * 49 + ia) * 49 + ja];
    }
}

__global__ __launch_bounds__(256, 2) void attn_kernel(
    const float* __restrict__ x,
    const float* __restrict__ qkv_w, const float* __restrict__ qkv_b,
    const float* __restrict__ proj_w, const float* __restrict__ proj_b,
    float* __restrict__ out) {
    extern __shared__ float smem[];
    float* xs = smem;                          // 25 * 129  (also reused as attention-output buffer)
    float* qk = smem + NTOK * XS_STRIDE;       // 25 * 385  (q | k | v concatenated per token)
    float* ws = qk + NTOK * QK_STRIDE;         // 128 * 17  (weight staging)

    int b = blockIdx.x;
    int tid = threadIdx.x;

    // ---- Stage 1: load x[b] (25 x 128) into smem ----
    const float* xb = x + (size_t)b * (NTOK * 128);
    for (int idx = tid; idx < NTOK * 128; idx += 256) {
        xs[(idx >> 7) * XS_STRIDE + (idx & 127)] = xb[idx];
    }
    __syncthreads();

    // thread tiling: 64 column-pairs x 4 token-quarters (7,6,6,6 tokens)
    int cp = tid & 63;
    int th = tid >> 6;
    int t0 = (th == 0) ? 0 : (7 + (th - 1) * 6);
    int nt = (th == 0) ? 7 : 6;

    // ---- Stage 2: qkv = x @ qkv_w.T + qkv_b  -> qk[25][384] ----
    for (int cc = 0; cc < 3; cc++) {
        float acc0[7], acc1[7];
#pragma unroll
        for (int u = 0; u < 7; u++) { acc0[u] = 0.f; acc1[u] = 0.f; }
        for (int kb = 0; kb < 128; kb += 16) {
            // stage 128 cols x 16 k of qkv_w into smem
#pragma unroll
            for (int u = 0; u < 8; u++) {
                int li = u * 256 + tid;
                int row = li >> 4, kk = li & 15;
                ws[row * WS_STRIDE + kk] = qkv_w[(cc * 128 + row) * 128 + kb + kk];
            }
            __syncthreads();
#pragma unroll
            for (int kk = 0; kk < 16; kk++) {
                float w0 = ws[(2 * cp) * WS_STRIDE + kk];
                float w1 = ws[(2 * cp + 1) * WS_STRIDE + kk];
#pragma unroll
                for (int u = 0; u < 7; u++) {
                    if (u < nt) {
                        float xv = xs[(t0 + u) * XS_STRIDE + kb + kk];
                        acc0[u] += xv * w0;
                        acc1[u] += xv * w1;
                    }
                }
            }
            __syncthreads();
        }
        int c = cc * 128 + 2 * cp;
        float b0 = qkv_b[c], b1 = qkv_b[c + 1];
        for (int u = 0; u < nt; u++) {
            qk[(t0 + u) * QK_STRIDE + c] = acc0[u] + b0;
            qk[(t0 + u) * QK_STRIDE + c + 1] = acc1[u] + b1;
        }
    }
    __syncthreads();

    // ---- Stage 3: attention (100 threads: one per (head, query-row)) ----
    const float scale = 0.17677669529663687f;  // 32^-0.5
    if (tid < 100) {
        int h = tid / 25, i = tid % 25;
        int rot = 8 * h;  // per-head dim rotation to decorrelate smem banks
        float qv[32];
#pragma unroll
        for (int d = 0; d < 32; d++) {
            int dd = (d + rot) & 31;
            qv[d] = qk[i * QK_STRIDE + h * 32 + dd] * scale;
        }
        const float* gb = g_bias + (((b & 63) * 4 + h) * 25 + i) * 25;
        float s[25];
        float m = -1e30f;
        for (int j = 0; j < 25; j++) {
            float acc = gb[j];
#pragma unroll
            for (int d = 0; d < 32; d++) {
                int dd = (d + rot) & 31;
                acc += qv[d] * qk[j * QK_STRIDE + 128 + h * 32 + dd];
            }
            s[j] = acc;
            m = fmaxf(m, acc);
        }
        float sum = 0.f;
        for (int j = 0; j < 25; j++) { s[j] = __expf(s[j] - m); sum += s[j]; }
        float inv = 1.f / sum;
        float o[32];
#pragma unroll
        for (int d = 0; d < 32; d++) o[d] = 0.f;
        for (int j = 0; j < 25; j++) {
            float p = s[j] * inv;
#pragma unroll
            for (int d = 0; d < 32; d++) {
                int dd = (d + rot) & 31;
                o[d] += p * qk[j * QK_STRIDE + 256 + h * 32 + dd];
            }
        }
        // write attention output into xs (x no longer needed)
#pragma unroll
        for (int d = 0; d < 32; d++) {
            int dd = (d + rot) & 31;
            xs[i * XS_STRIDE + h * 32 + dd] = o[d];
        }
    }
    __syncthreads();

    // ---- Stage 4: out = attn_out @ proj_w.T + proj_b ----
    {
        float acc0[7], acc1[7];
#pragma unroll
        for (int u = 0; u < 7; u++) { acc0[u] = 0.f; acc1[u] = 0.f; }
        for (int kb = 0; kb < 128; kb += 16) {
#pragma unroll
            for (int u = 0; u < 8; u++) {
                int li = u * 256 + tid;
                int row = li >> 4, kk = li & 15;
                ws[row * WS_STRIDE + kk] = proj_w[row * 128 + kb + kk];
            }
            __syncthreads();
#pragma unroll
            for (int kk = 0; kk < 16; kk++) {
                float w0 = ws[(2 * cp) * WS_STRIDE + kk];
                float w1 = ws[(2 * cp + 1) * WS_STRIDE + kk];
#pragma unroll
                for (int u = 0; u < 7; u++) {
                    if (u < nt) {
                        float xv = xs[(t0 + u) * XS_STRIDE + kb + kk];
                        acc0[u] += xv * w0;
                        acc1[u] += xv * w1;
                    }
                }
            }
            __syncthreads();
        }
        int c = 2 * cp;
        float b0 = proj_b[c], b1 = proj_b[c + 1];
        float* ob = out + (size_t)b * (NTOK * 128);
        for (int u = 0; u < nt; u++) {
            ob[(t0 + u) * 128 + c] = acc0[u] + b0;
            ob[(t0 + u) * 128 + c + 1] = acc1[u] + b1;
        }
    }
}

extern "C" void kernel_launch(void* const* d_in, const int* in_sizes, int n_in,
                              void* d_out, int out_size) {
    const float* x          = (const float*)d_in[0];
    const float* mask       = (const float*)d_in[1];
    const int*   ids_keep   = (const int*)d_in[2];
    const float* qkv_w      = (const float*)d_in[3];
    const float* qkv_b      = (const float*)d_in[4];
    const float* proj_w     = (const float*)d_in[5];
    const float* proj_b     = (const float*)d_in[6];
    const float* bias_table = (const float*)d_in[7];
    const int*   rel_index  = (const int*)d_in[8];
    float* out = (float*)d_out;

    bias_kernel<<<64, 256>>>(mask, ids_keep, bias_table, rel_index);

    size_t smem = (size_t)(NTOK * XS_STRIDE + NTOK * QK_STRIDE + 128 * WS_STRIDE) * sizeof(float);
    cudaFuncSetAttribute(attn_kernel, cudaFuncAttributeMaxDynamicSharedMemorySize, (int)smem);
    attn_kernel<<<4096, 256, smem>>>(x, qkv_w, qkv_b, proj_w, proj_b, out);
}

// round 3
// speedup vs baseline: 2.2165x; 2.2165x over previous
#include <cuda_runtime.h>

#define NTOK 25
#define XS  132    // xs row stride (floats), float4-aligned
#define QKS 388    // qk row stride (floats)
#define WSS 68     // ws row stride (floats): 64 k + 4 pad -> conflict-free LDS.128

typedef unsigned long long u64;

// Precomputed combined (relative-position bias + window mask) per (window, head, i, j)
__device__ float g_bias[64 * 4 * 25 * 25];

__global__ void bias_kernel(const float* __restrict__ mask, const int* __restrict__ ids_keep,
                            const float* __restrict__ bias_table, const int* __restrict__ rel_index) {
    int w = blockIdx.x;
    __shared__ int ids[NTOK];
    if (threadIdx.x < NTOK) ids[threadIdx.x] = ids_keep[w * NTOK + threadIdx.x];
    __syncthreads();
    for (int e = threadIdx.x; e < 4 * NTOK * NTOK; e += blockDim.x) {
        int h = e / (NTOK * NTOK);
        int r = e % (NTOK * NTOK);
        int i = r / NTOK, j = r % NTOK;
        int ia = ids[i], ja = ids[j];
        int rel = rel_index[ia * 49 + ja];
        g_bias[(w * 4 + h) * 625 + r] = bias_table[rel * 4 + h] + mask[(w * 49 + ia) * 49 + ja];
    }
}

__device__ __forceinline__ void ffma2(u64& acc, u64 a, u64 b) {
    asm("fma.rn.f32x2 %0, %1, %2, %0;" : "+l"(acc) : "l"(a), "l"(b));
}
__device__ __forceinline__ float fsum2(u64 v) {
    return __uint_as_float((unsigned)v) + __uint_as_float((unsigned)(v >> 32));
}
__device__ __forceinline__ u64 dup(float x) {
    u64 r; unsigned bb = __float_as_uint(x);
    asm("mov.b64 %0, {%1, %1};" : "=l"(r) : "r"(bb));
    return r;
}

__global__ __launch_bounds__(256, 2) void attn_kernel(
    const float* __restrict__ x,
    const float* __restrict__ qkv_w, const float* __restrict__ qkv_b,
    const float* __restrict__ proj_w, const float* __restrict__ proj_b,
    float* __restrict__ out) {
    extern __shared__ float smem[];
    float* xs = smem;                   // 25 * 132  (input, later attention output)
    float* qk = smem + NTOK * XS;       // 25 * 388  (q | k | v per token)
    float* ws = qk + NTOK * QKS;        // 128 * 68  (64-wide K chunk of weights)

    int b = blockIdx.x;
    int tid = threadIdx.x;

    // ---- Stage 1: x[b] (25 x 128) -> smem ----
    const float* xb = x + (size_t)b * (NTOK * 128);
    for (int idx = tid; idx < NTOK * 128; idx += 256)
        xs[(idx >> 7) * XS + (idx & 127)] = xb[idx];
    __syncthreads();

    // GEMM thread tiling: 64 col-groups (cols cg, cg+64) x 4 token groups (7,6,6,6)
    int cg = tid & 63;
    int tg = tid >> 6;
    int t0 = tg ? (7 + 6 * (tg - 1)) : 0;
    int nt = tg ? 6 : 7;

    // weight staging mapping: each thread copies 8 float4 of one column's half-row
    int sc = tid & 127;
    int sq = (tid >> 7) * 8;

    // ---- Stage 2: qkv = x @ qkv_w.T + qkv_b ----
    for (int cc = 0; cc < 3; cc++) {
        u64 acc0[7], acc1[7];
#pragma unroll
        for (int u = 0; u < 7; u++) { acc0[u] = 0ull; acc1[u] = 0ull; }
        for (int half = 0; half < 2; half++) {
            const float* wsrc = qkv_w + (size_t)(cc * 128 + sc) * 128 + half * 64;
#pragma unroll
            for (int j = 0; j < 8; j++)
                *(float4*)&ws[sc * WSS + (sq + j) * 4] = *(const float4*)&wsrc[(sq + j) * 4];
            __syncthreads();
#pragma unroll
            for (int kq = 0; kq < 16; kq++) {
                ulonglong2 w0 = *(const ulonglong2*)&ws[cg * WSS + kq * 4];
                ulonglong2 w1 = *(const ulonglong2*)&ws[(cg + 64) * WSS + kq * 4];
#pragma unroll
                for (int u = 0; u < 7; u++) {
                    if (u < nt) {
                        ulonglong2 xv = *(const ulonglong2*)&xs[(t0 + u) * XS + half * 64 + kq * 4];
                        ffma2(acc0[u], w0.x, xv.x);
                        ffma2(acc0[u], w0.y, xv.y);
                        ffma2(acc1[u], w1.x, xv.x);
                        ffma2(acc1[u], w1.y, xv.y);
                    }
                }
            }
            __syncthreads();
        }
        float b0 = qkv_b[cc * 128 + cg];
        float b1 = qkv_b[cc * 128 + cg + 64];
        for (int u = 0; u < nt; u++) {
            qk[(t0 + u) * QKS + cc * 128 + cg]      = fsum2(acc0[u]) + b0;
            qk[(t0 + u) * QKS + cc * 128 + cg + 64] = fsum2(acc1[u]) + b1;
        }
    }
    __syncthreads();

    // ---- Stage 3: attention (100 threads: one per (head, query-row)) ----
    const float scale = 0.17677669529663687f;  // 32^-0.5 (applied post-dot)
    if (tid < 100) {
        int h = tid / 25, i = tid - h * 25;
        const float* qrow = qk + i * QKS + h * 32;
        u64 qv[16];
#pragma unroll
        for (int q = 0; q < 8; q++) {
            int qq = (q + 2 * h) & 7;  // per-head 16B rotation: decorrelates banks across heads
            ulonglong2 t = *(const ulonglong2*)&qrow[qq * 4];
            qv[2 * q] = t.x; qv[2 * q + 1] = t.y;
        }
        const float* gb = g_bias + (((b & 63) * 4 + h) * 25 + i) * 25;
        float s[25];
        float m = -1e30f;
        for (int j = 0; j < 25; j++) {
            const float* krow = qk + j * QKS + 128 + h * 32;
            u64 acc = 0ull;
#pragma unroll
            for (int q = 0; q < 8; q++) {
                int qq = (q + 2 * h) & 7;
                ulonglong2 t = *(const ulonglong2*)&krow[qq * 4];
                ffma2(acc, qv[2 * q], t.x);
                ffma2(acc, qv[2 * q + 1], t.y);
            }
            float sv = fsum2(acc) * scale + gb[j];
            s[j] = sv;
            m = fmaxf(m, sv);
        }
        float sum = 0.f;
        for (int j = 0; j < 25; j++) { s[j] = __expf(s[j] - m); sum += s[j]; }
        float inv = 1.f / sum;
        u64 o[16];
#pragma unroll
        for (int q = 0; q < 16; q++) o[q] = 0ull;
        for (int j = 0; j < 25; j++) {
            u64 pp = dup(s[j] * inv);
            const float* vrow = qk + j * QKS + 256 + h * 32;
#pragma unroll
            for (int q = 0; q < 8; q++) {
                int qq = (q + 2 * h) & 7;
                ulonglong2 t = *(const ulonglong2*)&vrow[qq * 4];
                ffma2(o[2 * q], pp, t.x);
                ffma2(o[2 * q + 1], pp, t.y);
            }
        }
        float* orow = xs + i * XS + h * 32;
#pragma unroll
        for (int q = 0; q < 8; q++) {
            int qq = (q + 2 * h) & 7;
            ulonglong2 t;
            t.x = o[2 * q]; t.y = o[2 * q + 1];
            *(ulonglong2*)&orow[qq * 4] = t;
        }
    }
    __syncthreads();

    // ---- Stage 4: out = attn_out @ proj_w.T + proj_b ----
    {
        u64 acc0[7], acc1[7];
#pragma unroll
        for (int u = 0; u < 7; u++) { acc0[u] = 0ull; acc1[u] = 0ull; }
        for (int half = 0; half < 2; half++) {
            const float* wsrc = proj_w + (size_t)sc * 128 + half * 64;
#pragma unroll
            for (int j = 0; j < 8; j++)
                *(float4*)&ws[sc * WSS + (sq + j) * 4] = *(const float4*)&wsrc[(sq + j) * 4];
            __syncthreads();
#pragma unroll
            for (int kq = 0; kq < 16; kq++) {
                ulonglong2 w0 = *(const ulonglong2*)&ws[cg * WSS + kq * 4];
                ulonglong2 w1 = *(const ulonglong2*)&ws[(cg + 64) * WSS + kq * 4];
#pragma unroll
                for (int u = 0; u < 7; u++) {
                    if (u < nt) {
                        ulonglong2 xv = *(const ulonglong2*)&xs[(t0 + u) * XS + half * 64 + kq * 4];
                        ffma2(acc0[u], w0.x, xv.x);
                        ffma2(acc0[u], w0.y, xv.y);
                        ffma2(acc1[u], w1.x, xv.x);
                        ffma2(acc1[u], w1.y, xv.y);
                    }
                }
            }
            __syncthreads();
        }
        float b0 = proj_b[cg], b1 = proj_b[cg + 64];
        float* ob = out + (size_t)b * (NTOK * 128);
        for (int u = 0; u < nt; u++) {
            ob[(t0 + u) * 128 + cg]      = fsum2(acc0[u]) + b0;
            ob[(t0 + u) * 128 + cg + 64] = fsum2(acc1[u]) + b1;
        }
    }
}

extern "C" void kernel_launch(void* const* d_in, const int* in_sizes, int n_in,
                              void* d_out, int out_size) {
    const float* x          = (const float*)d_in[0];
    const float* mask       = (const float*)d_in[1];
    const int*   ids_keep   = (const int*)d_in[2];
    const float* qkv_w      = (const float*)d_in[3];
    const float* qkv_b      = (const float*)d_in[4];
    const float* proj_w     = (const float*)d_in[5];
    const float* proj_b     = (const float*)d_in[6];
    const float* bias_table = (const float*)d_in[7];
    const int*   rel_index  = (const int*)d_in[8];
    float* out = (float*)d_out;

    bias_kernel<<<64, 256>>>(mask, ids_keep, bias_table, rel_index);

    size_t smem = (size_t)(NTOK * XS + NTOK * QKS + 128 * WSS) * sizeof(float);
    cudaFuncSetAttribute(attn_kernel, cudaFuncAttributeMaxDynamicSharedMemorySize, (int)smem);
    attn_kernel<<<4096, 256, smem>>>(x, qkv_w, qkv_b, proj_w, proj_b, out);
}